// round 8
// baseline (speedup 1.0000x reference)
#include <cuda_runtime.h>
#include <cuda_fp16.h>
#include <math.h>
#include <stdint.h>

// ---------------- problem dims ----------------
#define BDIM 4
#define TDIM 2048
#define DDIM 512
#define EDIM 4
#define CDIM 1024
#define HEDIM 512
#define ODIM 512
#define ECDIM 4096
#define EHE (EDIM * HEDIM)   // 2048

typedef __half f16;

// ---------------- operand storage (no cudaMalloc allowed) ----------------
__device__ f16 g_dmT[(size_t)BDIM * ECDIM * TDIM];   // dmask^T  [B][E*C][T]
__device__ f16 g_cmb[(size_t)BDIM * TDIM * ECDIM];   // combine  [B][T][E*C]
__device__ f16 g_x  [(size_t)BDIM * TDIM * DDIM];
__device__ f16 g_w1 [(size_t)EDIM * DDIM * HEDIM];
__device__ f16 g_w2 [(size_t)EDIM * HEDIM * ODIM];   // == [EHE][O]
__device__ f16 g_u  [(size_t)BDIM * EDIM * TDIM * HEDIM];  // u = x @ w1_e
__device__ f16 g_h  [(size_t)BDIM * ECDIM * HEDIM];
__device__ f16 g_z  [(size_t)BDIM * TDIM * EHE];     // z = comb_e @ h_e

// ---------------- helpers ----------------
__device__ __forceinline__ uint32_t pack_h2(float a, float b) {
    __half2 p = __floats2half2_rn(a, b);
    return *reinterpret_cast<uint32_t*>(&p);
}

// ---------------- conversion kernels ----------------
__global__ void conv_ew(const float* __restrict__ s, f16* __restrict__ d,
                        long long n4) {
    long long i = (long long)blockIdx.x * blockDim.x + threadIdx.x;
    if (i < n4) {
        float4 v = reinterpret_cast<const float4*>(s)[i];
        uint2 h;
        h.x = pack_h2(v.x, v.y); h.y = pack_h2(v.z, v.w);
        reinterpret_cast<uint2*>(d)[i] = h;
    }
}
// src [R][Cc] per batch -> dst [Cc][R] single fp16
__global__ void tr_one(const float* __restrict__ s, f16* __restrict__ d,
                       int R, int Cc) {
    __shared__ float t[64][33];
    const int c0 = blockIdx.x * 32, r0 = blockIdx.y * 64;
    const size_t zoff = (size_t)blockIdx.z * R * Cc;
    const float* S = s + zoff;
    const int tx = threadIdx.x & 31, ty = threadIdx.x >> 5;
#pragma unroll
    for (int i = 0; i < 8; i++) {
        int r = ty + i * 8;
        t[r][tx] = S[(size_t)(r0 + r) * Cc + c0 + tx];
    }
    __syncthreads();
    const int rr = threadIdx.x >> 3, pair = threadIdx.x & 7;
#pragma unroll
    for (int i = 0; i < 4; i++) {
        int tcol = (pair + i * 8) * 2;
        float a = t[tcol][rr], b = t[tcol + 1][rr];
        size_t o = zoff + (size_t)(c0 + rr) * R + r0 + tcol;
        *reinterpret_cast<uint32_t*>(d + o) = pack_h2(a, b);
    }
}

// ---------------- GEMM tile config ----------------
constexpr int BM = 128, BN = 256, BK = 32;
constexpr int THREADS = 256;
constexpr int OFF_B  = 8192;
constexpr int STAGE  = 24576;
constexpr int NSTG   = 4;
constexpr int SMEM_TOTAL = NSTG * STAGE;   // 96 KB

__device__ __forceinline__ int a_off(int m, int kc) {   // rows 64B
    return m * 64 + ((kc ^ ((m >> 1) & 3)) << 4);
}
__device__ __forceinline__ int b_off(int k, int nc) {   // rows 512B
    return k * 512 + ((nc ^ (k & 7)) << 4);
}
__device__ __forceinline__ uint32_t smem_u32(const void* p) {
    uint32_t a;
    asm("{ .reg .u64 t; cvta.to.shared.u64 t, %1; cvt.u32.u64 %0, t; }"
        : "=r"(a) : "l"(p));
    return a;
}
__device__ __forceinline__ void ldsm4(uint32_t* r, uint32_t addr) {
    asm volatile("ldmatrix.sync.aligned.m8n8.x4.shared.b16 {%0,%1,%2,%3}, [%4];"
                 : "=r"(r[0]), "=r"(r[1]), "=r"(r[2]), "=r"(r[3]) : "r"(addr));
}
__device__ __forceinline__ void ldsm4t(uint32_t* r, uint32_t addr) {
    asm volatile("ldmatrix.sync.aligned.m8n8.x4.trans.shared.b16 {%0,%1,%2,%3}, [%4];"
                 : "=r"(r[0]), "=r"(r[1]), "=r"(r[2]), "=r"(r[3]) : "r"(addr));
}
__device__ __forceinline__ void mma_f16(float* d, const uint32_t* a, const uint32_t* b) {
    asm volatile(
        "mma.sync.aligned.m16n8k16.row.col.f32.f16.f16.f32 "
        "{%0,%1,%2,%3}, {%4,%5,%6,%7}, {%8,%9}, {%0,%1,%2,%3};"
        : "+f"(d[0]), "+f"(d[1]), "+f"(d[2]), "+f"(d[3])
        : "r"(a[0]), "r"(a[1]), "r"(a[2]), "r"(a[3]), "r"(b[0]), "r"(b[1]));
}
__device__ __forceinline__ void cp16(uint32_t dst, const void* src) {
    asm volatile("cp.async.cg.shared.global [%0], [%1], 16;" :: "r"(dst), "l"(src));
}
__device__ __forceinline__ void cp_commit() {
    asm volatile("cp.async.commit_group;" ::: "memory");
}
template<int N>
__device__ __forceinline__ void cp_wait() {
    asm volatile("cp.async.wait_group %0;" :: "n"(N) : "memory");
}

// ---------------- main GEMM kernel ----------------
// CTA 128x256, warp tile 64x64, 1-pass fp16, fp32 accum.
// Two-level z indexing: off = (z/zMod)*s1 + (z%zMod)*s2 for A, B, C; bias by zr.
// OUTM: 0 = fp32 out, 2 = single f16 out.
template<int OUTM, bool GELU_, bool BIAS_>
__global__ __launch_bounds__(THREADS, 1)
void moe_gemm(const f16* __restrict__ Ab, const f16* __restrict__ Bb,
              float* __restrict__ Cf, f16* __restrict__ Ch,
              const float* __restrict__ biasBase,
              int lda, int ldb, int ldc, int KT, int zMod,
              long long sA1, long long sA2, long long sB1, long long sB2,
              long long sC1, long long sC2, long long sBias2)
{
    extern __shared__ char smem[];
    const int tid  = threadIdx.x;
    const int lane = tid & 31;
    const int wid  = tid >> 5;
    const int wm   = (wid & 1) * 64;
    const int wn   = (wid >> 1) * 64;

    const int z = blockIdx.z;
    const int zq = z / zMod, zr = z % zMod;
    const f16* A = Ab + zq * sA1 + zr * sA2;
    const f16* B = Bb + zq * sB1 + zr * sB2;
    const long long coff = zq * sC1 + zr * sC2;
    const float* bias = BIAS_ ? biasBase + zr * sBias2 : nullptr;

    const int m0 = blockIdx.y * BM;
    const int n0 = blockIdx.x * BN;
    const uint32_t sbase = smem_u32(smem);

    float acc[4][8][4];
#pragma unroll
    for (int i = 0; i < 4; i++)
#pragma unroll
        for (int j = 0; j < 8; j++)
#pragma unroll
            for (int c = 0; c < 4; c++) acc[i][j][c] = 0.f;

    auto issue = [&](int it) {
        if (it < KT) {
            const uint32_t st = sbase + (it & (NSTG - 1)) * STAGE;
            const int k0 = it * BK;
#pragma unroll
            for (int i = 0; i < 2; i++) {
                int c = tid + i * THREADS;
                int m = c >> 2, kc = c & 3;
                cp16(st + a_off(m, kc),
                     A + (size_t)(m0 + m) * lda + k0 + kc * 8);
            }
#pragma unroll
            for (int i = 0; i < 4; i++) {
                int c = tid + i * THREADS;
                int k = c >> 5, nc = c & 31;
                cp16(st + OFF_B + b_off(k, nc),
                     B + (size_t)(k0 + k) * ldb + n0 + nc * 8);
            }
        }
        cp_commit();
    };

    issue(0); issue(1); issue(2);

    for (int it = 0; it < KT; ++it) {
        cp_wait<2>();
        __syncthreads();
        issue(it + 3);

        const uint32_t cur = sbase + (it & (NSTG - 1)) * STAGE;
#pragma unroll
        for (int kh = 0; kh < 2; kh++) {
            uint32_t ar[4][4];
#pragma unroll
            for (int mf = 0; mf < 4; mf++) {
                int row = wm + mf * 16 + (lane & 15);
                int chunk = kh * 2 + (lane >> 4);
                ldsm4(ar[mf], cur + a_off(row, chunk));
            }
            uint32_t br[4][4];
#pragma unroll
            for (int nb = 0; nb < 4; nb++) {
                int k = kh * 16 + ((lane >> 3) & 1) * 8 + (lane & 7);
                int nchunk = ((wn + nb * 16) >> 3) + (lane >> 4);
                ldsm4t(br[nb], cur + OFF_B + b_off(k, nchunk));
            }
#pragma unroll
            for (int mf = 0; mf < 4; mf++)
#pragma unroll
                for (int nf = 0; nf < 8; nf++)
                    mma_f16(acc[mf][nf], ar[mf], &br[nf >> 1][(nf & 1) * 2]);
        }
    }

    // ---- epilogue ----
    const int g = lane >> 2, t = lane & 3;
#pragma unroll
    for (int mf = 0; mf < 4; mf++) {
#pragma unroll
        for (int nf = 0; nf < 8; nf++) {
            int row = m0 + wm + mf * 16 + g;
            int col = n0 + wn + nf * 8 + t * 2;
            float v0 = acc[mf][nf][0], v1 = acc[mf][nf][1];
            float v2 = acc[mf][nf][2], v3 = acc[mf][nf][3];
            if (BIAS_) {
                float2 bv = *reinterpret_cast<const float2*>(bias + col);
                v0 += bv.x; v1 += bv.y; v2 += bv.x; v3 += bv.y;
            }
            if (GELU_) {
                v0 = 0.5f * v0 * (1.0f + erff(v0 * 0.70710678118654752f));
                v1 = 0.5f * v1 * (1.0f + erff(v1 * 0.70710678118654752f));
                v2 = 0.5f * v2 * (1.0f + erff(v2 * 0.70710678118654752f));
                v3 = 0.5f * v3 * (1.0f + erff(v3 * 0.70710678118654752f));
            }
            size_t o0 = (size_t)(coff + (size_t)row * ldc + col);
            size_t o1 = (size_t)(coff + (size_t)(row + 8) * ldc + col);
            if (OUTM == 0) {
                *reinterpret_cast<float2*>(Cf + o0) = make_float2(v0, v1);
                *reinterpret_cast<float2*>(Cf + o1) = make_float2(v2, v3);
            } else {
                *reinterpret_cast<uint32_t*>(Ch + o0) = pack_h2(v0, v1);
                *reinterpret_cast<uint32_t*>(Ch + o1) = pack_h2(v2, v3);
            }
        }
    }
}

// ---------------- launcher ----------------
extern "C" void kernel_launch(void* const* d_in, const int* in_sizes, int n_in,
                              void* d_out, int out_size)
{
    const float* x     = (const float*)d_in[0];
    const float* dmask = (const float*)d_in[1];
    const float* comb  = (const float*)d_in[2];
    const float* w1    = (const float*)d_in[3];
    const float* b1    = (const float*)d_in[4];
    const float* w2f   = (const float*)d_in[5];
    const float* b2    = (const float*)d_in[6];
    float* out = (float*)d_out;

    f16 *dmT, *cmb, *xs, *w1s, *w2s, *uu, *hh, *zz;
    cudaGetSymbolAddress((void**)&dmT, g_dmT);
    cudaGetSymbolAddress((void**)&cmb, g_cmb);
    cudaGetSymbolAddress((void**)&xs,  g_x);
    cudaGetSymbolAddress((void**)&w1s, g_w1);
    cudaGetSymbolAddress((void**)&w2s, g_w2);
    cudaGetSymbolAddress((void**)&uu,  g_u);
    cudaGetSymbolAddress((void**)&hh,  g_h);
    cudaGetSymbolAddress((void**)&zz,  g_z);

    cudaFuncSetAttribute(moe_gemm<2, false, false>,
                         cudaFuncAttributeMaxDynamicSharedMemorySize, SMEM_TOTAL);
    cudaFuncSetAttribute(moe_gemm<2, true,  true>,
                         cudaFuncAttributeMaxDynamicSharedMemorySize, SMEM_TOTAL);
    cudaFuncSetAttribute(moe_gemm<0, false, true>,
                         cudaFuncAttributeMaxDynamicSharedMemorySize, SMEM_TOTAL);

    // ---- conversions (all single fp16) ----
    tr_one<<<dim3(ECDIM / 32, TDIM / 64, BDIM), 256>>>(dmask, dmT, TDIM, ECDIM);
    {
        long long n4 = (long long)BDIM * TDIM * ECDIM / 4;
        conv_ew<<<(unsigned)((n4 + 255) / 256), 256>>>(comb, cmb, n4);
    }
    {
        long long n4 = (long long)BDIM * TDIM * DDIM / 4;
        conv_ew<<<(unsigned)((n4 + 255) / 256), 256>>>(x, xs, n4);
    }
    {
        long long n4 = (long long)EDIM * DDIM * HEDIM / 4;
        conv_ew<<<(unsigned)((n4 + 255) / 256), 256>>>(w1, w1s, n4);
        conv_ew<<<(unsigned)((n4 + 255) / 256), 256>>>(w2f, w2s, n4);
    }

    // ---- P1: u[b][e][T][HE] = x[b][T][D] @ w1[e][D][HE] ----
    // z = b*E + e : A uses zq (b), B uses zr (e), C uses both
    moe_gemm<2, false, false>
        <<<dim3(HEDIM / BN, TDIM / BM, BDIM * EDIM), THREADS, SMEM_TOTAL>>>(
        xs, w1s, nullptr, uu, nullptr,
        DDIM, HEDIM, HEDIM, DDIM / BK, /*zMod*/ EDIM,
        (long long)TDIM * DDIM, 0,
        0, (long long)DDIM * HEDIM,
        (long long)EDIM * TDIM * HEDIM, (long long)TDIM * HEDIM,
        0);

    // ---- P2: h[b][e][C][HE] = gelu(dmT_{b,e}[C][T] @ u_{b,e}[T][HE] + b1_e) ----
    // dmT slice: base + b*(EC*T) + e*(C*T), lda = T
    moe_gemm<2, true, true>
        <<<dim3(HEDIM / BN, CDIM / BM, BDIM * EDIM), THREADS, SMEM_TOTAL>>>(
        dmT, uu, nullptr, hh, b1,
        TDIM, HEDIM, HEDIM, TDIM / BK, /*zMod*/ EDIM,
        (long long)ECDIM * TDIM, (long long)CDIM * TDIM,
        (long long)EDIM * TDIM * HEDIM, (long long)TDIM * HEDIM,
        (long long)EDIM * CDIM * HEDIM, (long long)CDIM * HEDIM,
        (long long)HEDIM);

    // ---- P3: z[b][T][e*HE+he] = comb_{b,e}[T][C] @ h_{b,e}[C][HE] ----
    moe_gemm<2, false, false>
        <<<dim3(HEDIM / BN, TDIM / BM, BDIM * EDIM), THREADS, SMEM_TOTAL>>>(
        cmb, hh, nullptr, zz, nullptr,
        ECDIM, HEDIM, EHE, CDIM / BK, /*zMod*/ EDIM,
        (long long)TDIM * ECDIM, (long long)CDIM,
        (long long)EDIM * CDIM * HEDIM, (long long)CDIM * HEDIM,
        (long long)TDIM * EHE, (long long)HEDIM,
        0);

    // ---- P4: out[b][T][O] = z[b][T][EHE] @ w2[EHE][O] + b2 ----
    moe_gemm<0, false, true>
        <<<dim3(ODIM / BN, TDIM / BM, BDIM), THREADS, SMEM_TOTAL>>>(
        zz, w2s, out, nullptr, b2,
        EHE, ODIM, ODIM, EHE / BK, /*zMod*/ 1,
        (long long)TDIM * EHE, 0, 0, 0,
        (long long)TDIM * ODIM, 0, 0);
}

// round 9
// speedup vs baseline: 1.1717x; 1.1717x over previous
#include <cuda_runtime.h>
#include <cuda_fp16.h>
#include <math.h>
#include <stdint.h>

// ---------------- problem dims ----------------
#define BDIM 4
#define TDIM 2048
#define DDIM 512
#define EDIM 4
#define CDIM 1024
#define HEDIM 512
#define ODIM 512
#define ECDIM 4096

typedef __half f16;

// ---------------- operand storage (no cudaMalloc allowed) ----------------
__device__ f16 g_dmT[(size_t)BDIM * ECDIM * TDIM];   // dmask^T  [B][E*C][T]
__device__ f16 g_cmb[(size_t)BDIM * TDIM * ECDIM];   // combine  [B][T][E*C]
__device__ f16 g_x  [(size_t)BDIM * TDIM * DDIM];
__device__ f16 g_w1 [(size_t)EDIM * DDIM * HEDIM];
__device__ f16 g_w2 [(size_t)EDIM * HEDIM * ODIM];
__device__ f16 g_xd [(size_t)BDIM * ECDIM * DDIM];   // dispatch result
__device__ f16 g_h  [(size_t)BDIM * ECDIM * HEDIM];  // gelu(fc1)
__device__ f16 g_y  [(size_t)BDIM * ECDIM * ODIM];   // fc2 result

// ---------------- helpers ----------------
__device__ __forceinline__ uint32_t pack_h2(float a, float b) {
    __half2 p = __floats2half2_rn(a, b);
    return *reinterpret_cast<uint32_t*>(&p);
}

// ---------------- conversion kernels ----------------
__global__ void conv_ew(const float* __restrict__ s, f16* __restrict__ d,
                        long long n4) {
    long long i = (long long)blockIdx.x * blockDim.x + threadIdx.x;
    if (i < n4) {
        float4 v = reinterpret_cast<const float4*>(s)[i];
        uint2 h;
        h.x = pack_h2(v.x, v.y); h.y = pack_h2(v.z, v.w);
        reinterpret_cast<uint2*>(d)[i] = h;
    }
}
// src [R][Cc] per batch -> dst [Cc][R] single fp16
__global__ void tr_one(const float* __restrict__ s, f16* __restrict__ d,
                       int R, int Cc) {
    __shared__ float t[64][33];
    const int c0 = blockIdx.x * 32, r0 = blockIdx.y * 64;
    const size_t zoff = (size_t)blockIdx.z * R * Cc;
    const float* S = s + zoff;
    const int tx = threadIdx.x & 31, ty = threadIdx.x >> 5;
#pragma unroll
    for (int i = 0; i < 8; i++) {
        int r = ty + i * 8;
        t[r][tx] = S[(size_t)(r0 + r) * Cc + c0 + tx];
    }
    __syncthreads();
    const int rr = threadIdx.x >> 3, pair = threadIdx.x & 7;
#pragma unroll
    for (int i = 0; i < 4; i++) {
        int tcol = (pair + i * 8) * 2;
        float a = t[tcol][rr], b = t[tcol + 1][rr];
        size_t o = zoff + (size_t)(c0 + rr) * R + r0 + tcol;
        *reinterpret_cast<uint32_t*>(d + o) = pack_h2(a, b);
    }
}

// ---------------- GEMM tile config ----------------
constexpr int BM = 128, BN = 256, BK = 32;
constexpr int THREADS = 256;
constexpr int OFF_B  = 8192;
constexpr int STAGE  = 24576;
constexpr int NSTG   = 4;
constexpr int SMEM_TOTAL = NSTG * STAGE;   // 96 KB

__device__ __forceinline__ int a_off(int m, int kc) {   // rows 64B
    return m * 64 + ((kc ^ ((m >> 1) & 3)) << 4);
}
__device__ __forceinline__ int b_off(int k, int nc) {   // rows 512B
    return k * 512 + ((nc ^ (k & 7)) << 4);
}
__device__ __forceinline__ uint32_t smem_u32(const void* p) {
    uint32_t a;
    asm("{ .reg .u64 t; cvta.to.shared.u64 t, %1; cvt.u32.u64 %0, t; }"
        : "=r"(a) : "l"(p));
    return a;
}
__device__ __forceinline__ void ldsm4(uint32_t* r, uint32_t addr) {
    asm volatile("ldmatrix.sync.aligned.m8n8.x4.shared.b16 {%0,%1,%2,%3}, [%4];"
                 : "=r"(r[0]), "=r"(r[1]), "=r"(r[2]), "=r"(r[3]) : "r"(addr));
}
__device__ __forceinline__ void ldsm4t(uint32_t* r, uint32_t addr) {
    asm volatile("ldmatrix.sync.aligned.m8n8.x4.trans.shared.b16 {%0,%1,%2,%3}, [%4];"
                 : "=r"(r[0]), "=r"(r[1]), "=r"(r[2]), "=r"(r[3]) : "r"(addr));
}
__device__ __forceinline__ void mma_f16(float* d, const uint32_t* a, const uint32_t* b) {
    asm volatile(
        "mma.sync.aligned.m16n8k16.row.col.f32.f16.f16.f32 "
        "{%0,%1,%2,%3}, {%4,%5,%6,%7}, {%8,%9}, {%0,%1,%2,%3};"
        : "+f"(d[0]), "+f"(d[1]), "+f"(d[2]), "+f"(d[3])
        : "r"(a[0]), "r"(a[1]), "r"(a[2]), "r"(a[3]), "r"(b[0]), "r"(b[1]));
}
__device__ __forceinline__ void cp16(uint32_t dst, const void* src) {
    asm volatile("cp.async.cg.shared.global [%0], [%1], 16;" :: "r"(dst), "l"(src));
}
__device__ __forceinline__ void cp_commit() {
    asm volatile("cp.async.commit_group;" ::: "memory");
}
template<int N>
__device__ __forceinline__ void cp_wait() {
    asm volatile("cp.async.wait_group %0;" :: "n"(N) : "memory");
}

// ---------------- main GEMM kernel ----------------
// CTA 128x256, warp tile 64x64, 1-pass fp16, fp32 accum.
// Two-level z indexing: off = (z/zMod)*s1 + (z%zMod)*s2 for A, B, C; bias by zr.
// OUTM: 0 = fp32 out, 2 = single f16 out.
template<int OUTM, bool GELU_, bool BIAS_>
__global__ __launch_bounds__(THREADS, 1)
void moe_gemm(const f16* __restrict__ Ab, const f16* __restrict__ Bb,
              float* __restrict__ Cf, f16* __restrict__ Ch,
              const float* __restrict__ biasBase,
              int lda, int ldb, int ldc, int KT, int zMod,
              long long sA1, long long sA2, long long sB1, long long sB2,
              long long sC1, long long sC2, long long sBias2)
{
    extern __shared__ char smem[];
    const int tid  = threadIdx.x;
    const int lane = tid & 31;
    const int wid  = tid >> 5;
    const int wm   = (wid & 1) * 64;
    const int wn   = (wid >> 1) * 64;

    const int z = blockIdx.z;
    const int zq = z / zMod, zr = z % zMod;
    const f16* A = Ab + zq * sA1 + zr * sA2;
    const f16* B = Bb + zq * sB1 + zr * sB2;
    const long long coff = zq * sC1 + zr * sC2;
    const float* bias = BIAS_ ? biasBase + zr * sBias2 : nullptr;

    const int m0 = blockIdx.y * BM;
    const int n0 = blockIdx.x * BN;
    const uint32_t sbase = smem_u32(smem);

    float acc[4][8][4];
#pragma unroll
    for (int i = 0; i < 4; i++)
#pragma unroll
        for (int j = 0; j < 8; j++)
#pragma unroll
            for (int c = 0; c < 4; c++) acc[i][j][c] = 0.f;

    auto issue = [&](int it) {
        if (it < KT) {
            const uint32_t st = sbase + (it & (NSTG - 1)) * STAGE;
            const int k0 = it * BK;
#pragma unroll
            for (int i = 0; i < 2; i++) {
                int c = tid + i * THREADS;
                int m = c >> 2, kc = c & 3;
                cp16(st + a_off(m, kc),
                     A + (size_t)(m0 + m) * lda + k0 + kc * 8);
            }
#pragma unroll
            for (int i = 0; i < 4; i++) {
                int c = tid + i * THREADS;
                int k = c >> 5, nc = c & 31;
                cp16(st + OFF_B + b_off(k, nc),
                     B + (size_t)(k0 + k) * ldb + n0 + nc * 8);
            }
        }
        cp_commit();
    };

    issue(0); issue(1); issue(2);

    for (int it = 0; it < KT; ++it) {
        cp_wait<2>();
        __syncthreads();
        issue(it + 3);

        const uint32_t cur = sbase + (it & (NSTG - 1)) * STAGE;
#pragma unroll
        for (int kh = 0; kh < 2; kh++) {
            uint32_t ar[4][4];
#pragma unroll
            for (int mf = 0; mf < 4; mf++) {
                int row = wm + mf * 16 + (lane & 15);
                int chunk = kh * 2 + (lane >> 4);
                ldsm4(ar[mf], cur + a_off(row, chunk));
            }
            uint32_t br[4][4];
#pragma unroll
            for (int nb = 0; nb < 4; nb++) {
                int k = kh * 16 + ((lane >> 3) & 1) * 8 + (lane & 7);
                int nchunk = ((wn + nb * 16) >> 3) + (lane >> 4);
                ldsm4t(br[nb], cur + OFF_B + b_off(k, nchunk));
            }
#pragma unroll
            for (int mf = 0; mf < 4; mf++)
#pragma unroll
                for (int nf = 0; nf < 8; nf++)
                    mma_f16(acc[mf][nf], ar[mf], &br[nf >> 1][(nf & 1) * 2]);
        }
    }

    // ---- epilogue ----
    const int g = lane >> 2, t = lane & 3;
#pragma unroll
    for (int mf = 0; mf < 4; mf++) {
#pragma unroll
        for (int nf = 0; nf < 8; nf++) {
            int row = m0 + wm + mf * 16 + g;
            int col = n0 + wn + nf * 8 + t * 2;
            float v0 = acc[mf][nf][0], v1 = acc[mf][nf][1];
            float v2 = acc[mf][nf][2], v3 = acc[mf][nf][3];
            if (BIAS_) {
                float2 bv = *reinterpret_cast<const float2*>(bias + col);
                v0 += bv.x; v1 += bv.y; v2 += bv.x; v3 += bv.y;
            }
            if (GELU_) {
                v0 = 0.5f * v0 * (1.0f + erff(v0 * 0.70710678118654752f));
                v1 = 0.5f * v1 * (1.0f + erff(v1 * 0.70710678118654752f));
                v2 = 0.5f * v2 * (1.0f + erff(v2 * 0.70710678118654752f));
                v3 = 0.5f * v3 * (1.0f + erff(v3 * 0.70710678118654752f));
            }
            size_t o0 = (size_t)(coff + (size_t)row * ldc + col);
            size_t o1 = (size_t)(coff + (size_t)(row + 8) * ldc + col);
            if (OUTM == 0) {
                *reinterpret_cast<float2*>(Cf + o0) = make_float2(v0, v1);
                *reinterpret_cast<float2*>(Cf + o1) = make_float2(v2, v3);
            } else {
                *reinterpret_cast<uint32_t*>(Ch + o0) = pack_h2(v0, v1);
                *reinterpret_cast<uint32_t*>(Ch + o1) = pack_h2(v2, v3);
            }
        }
    }
}

// ---------------- launcher ----------------
extern "C" void kernel_launch(void* const* d_in, const int* in_sizes, int n_in,
                              void* d_out, int out_size)
{
    const float* x     = (const float*)d_in[0];
    const float* dmask = (const float*)d_in[1];
    const float* comb  = (const float*)d_in[2];
    const float* w1    = (const float*)d_in[3];
    const float* b1    = (const float*)d_in[4];
    const float* w2f   = (const float*)d_in[5];
    const float* b2    = (const float*)d_in[6];
    float* out = (float*)d_out;

    f16 *dmT, *cmb, *xs, *w1s, *w2s, *xd, *hh, *yy;
    cudaGetSymbolAddress((void**)&dmT, g_dmT);
    cudaGetSymbolAddress((void**)&cmb, g_cmb);
    cudaGetSymbolAddress((void**)&xs,  g_x);
    cudaGetSymbolAddress((void**)&w1s, g_w1);
    cudaGetSymbolAddress((void**)&w2s, g_w2);
    cudaGetSymbolAddress((void**)&xd,  g_xd);
    cudaGetSymbolAddress((void**)&hh,  g_h);
    cudaGetSymbolAddress((void**)&yy,  g_y);

    cudaFuncSetAttribute(moe_gemm<2, false, false>,
                         cudaFuncAttributeMaxDynamicSharedMemorySize, SMEM_TOTAL);
    cudaFuncSetAttribute(moe_gemm<2, true,  true>,
                         cudaFuncAttributeMaxDynamicSharedMemorySize, SMEM_TOTAL);
    cudaFuncSetAttribute(moe_gemm<0, false, true>,
                         cudaFuncAttributeMaxDynamicSharedMemorySize, SMEM_TOTAL);

    // ---- conversions (all single fp16) ----
    tr_one<<<dim3(ECDIM / 32, TDIM / 64, BDIM), 256>>>(dmask, dmT, TDIM, ECDIM);
    {
        long long n4 = (long long)BDIM * TDIM * ECDIM / 4;
        conv_ew<<<(unsigned)((n4 + 255) / 256), 256>>>(comb, cmb, n4);
    }
    {
        long long n4 = (long long)BDIM * TDIM * DDIM / 4;
        conv_ew<<<(unsigned)((n4 + 255) / 256), 256>>>(x, xs, n4);
    }
    {
        long long n4 = (long long)EDIM * DDIM * HEDIM / 4;
        conv_ew<<<(unsigned)((n4 + 255) / 256), 256>>>(w1, w1s, n4);
        conv_ew<<<(unsigned)((n4 + 255) / 256), 256>>>(w2f, w2s, n4);
    }

    // ---- K1: xd[b][EC][D] = dmT[b][EC][T] @ x[b][T][D] ----
    moe_gemm<2, false, false>
        <<<dim3(DDIM / BN, ECDIM / BM, BDIM), THREADS, SMEM_TOTAL>>>(
        dmT, xs, nullptr, xd, nullptr,
        TDIM, DDIM, DDIM, TDIM / BK, /*zMod*/ 1,
        (long long)ECDIM * TDIM, 0, (long long)TDIM * DDIM, 0,
        (long long)ECDIM * DDIM, 0, 0);

    // ---- K2: h[b,e][C][HE] = gelu(xd_{b,e}[C][D] @ w1_e[D][HE] + b1_e) ----
    moe_gemm<2, true, true>
        <<<dim3(HEDIM / BN, CDIM / BM, BDIM * EDIM), THREADS, SMEM_TOTAL>>>(
        xd, w1s, nullptr, hh, b1,
        DDIM, HEDIM, HEDIM, DDIM / BK, /*zMod*/ EDIM,
        (long long)EDIM * CDIM * DDIM, (long long)CDIM * DDIM,
        0, (long long)DDIM * HEDIM,
        (long long)EDIM * CDIM * HEDIM, (long long)CDIM * HEDIM,
        (long long)HEDIM);

    // ---- K3: y[b,e][C][O] = h_{b,e}[C][HE] @ w2_e[HE][O] ----
    moe_gemm<2, false, false>
        <<<dim3(ODIM / BN, CDIM / BM, BDIM * EDIM), THREADS, SMEM_TOTAL>>>(
        hh, w2s, nullptr, yy, nullptr,
        HEDIM, ODIM, ODIM, HEDIM / BK, /*zMod*/ EDIM,
        (long long)EDIM * CDIM * HEDIM, (long long)CDIM * HEDIM,
        0, (long long)HEDIM * ODIM,
        (long long)EDIM * CDIM * ODIM, (long long)CDIM * ODIM,
        0);

    // ---- K4: out[b][T][O] = comb[b][T][EC] @ y[b][EC][O] + b2 ----
    moe_gemm<0, false, true>
        <<<dim3(ODIM / BN, TDIM / BM, BDIM), THREADS, SMEM_TOTAL>>>(
        cmb, yy, out, nullptr, b2,
        ECDIM, ODIM, ODIM, ECDIM / BK, /*zMod*/ 1,
        (long long)TDIM * ECDIM, 0, (long long)ECDIM * ODIM, 0,
        (long long)TDIM * ODIM, 0, 0);
}

// round 10
// speedup vs baseline: 1.2526x; 1.0691x over previous
#include <cuda_runtime.h>
#include <cuda_fp16.h>
#include <math.h>
#include <stdint.h>

// ---------------- problem dims ----------------
#define BDIM 4
#define TDIM 2048
#define DDIM 512
#define EDIM 4
#define CDIM 1024
#define HEDIM 512
#define ODIM 512
#define ECDIM 4096

typedef __half f16;

// ---------------- operand storage (no cudaMalloc allowed) ----------------
__device__ f16 g_dmT[(size_t)BDIM * ECDIM * TDIM];   // dmask^T  [B][E*C][T]
__device__ f16 g_cmb[(size_t)BDIM * TDIM * ECDIM];   // combine  [B][T][E*C]
__device__ f16 g_x  [(size_t)BDIM * TDIM * DDIM];
__device__ f16 g_w1 [(size_t)EDIM * DDIM * HEDIM];
__device__ f16 g_w2 [(size_t)EDIM * HEDIM * ODIM];
__device__ f16 g_xd [(size_t)BDIM * ECDIM * DDIM];   // dispatch result
__device__ f16 g_h  [(size_t)BDIM * ECDIM * HEDIM];  // gelu(fc1)
__device__ f16 g_y  [(size_t)BDIM * ECDIM * ODIM];   // fc2 result

// ---------------- helpers ----------------
__device__ __forceinline__ uint32_t pack_h2(float a, float b) {
    __half2 p = __floats2half2_rn(a, b);
    return *reinterpret_cast<uint32_t*>(&p);
}

// ---------------- conversion kernels ----------------
__global__ void conv_ew(const float* __restrict__ s, f16* __restrict__ d,
                        long long n4) {
    long long i = (long long)blockIdx.x * blockDim.x + threadIdx.x;
    if (i < n4) {
        float4 v = reinterpret_cast<const float4*>(s)[i];
        uint2 h;
        h.x = pack_h2(v.x, v.y); h.y = pack_h2(v.z, v.w);
        reinterpret_cast<uint2*>(d)[i] = h;
    }
}
// src [R][Cc] per batch -> dst [Cc][R] single fp16
__global__ void tr_one(const float* __restrict__ s, f16* __restrict__ d,
                       int R, int Cc) {
    __shared__ float t[64][33];
    const int c0 = blockIdx.x * 32, r0 = blockIdx.y * 64;
    const size_t zoff = (size_t)blockIdx.z * R * Cc;
    const float* S = s + zoff;
    const int tx = threadIdx.x & 31, ty = threadIdx.x >> 5;
#pragma unroll
    for (int i = 0; i < 8; i++) {
        int r = ty + i * 8;
        t[r][tx] = S[(size_t)(r0 + r) * Cc + c0 + tx];
    }
    __syncthreads();
    const int rr = threadIdx.x >> 3, pair = threadIdx.x & 7;
#pragma unroll
    for (int i = 0; i < 4; i++) {
        int tcol = (pair + i * 8) * 2;
        float a = t[tcol][rr], b = t[tcol + 1][rr];
        size_t o = zoff + (size_t)(c0 + rr) * R + r0 + tcol;
        *reinterpret_cast<uint32_t*>(d + o) = pack_h2(a, b);
    }
}

// ---------------- GEMM tile config ----------------
constexpr int BM = 128, BN = 128, BK = 32;
constexpr int THREADS = 256;
constexpr int OFF_B  = 8192;
constexpr int STAGE  = 16384;
constexpr int NSTG   = 4;
constexpr int SMEM_TOTAL = NSTG * STAGE;   // 64 KB -> 2 CTAs/SM

__device__ __forceinline__ int a_off(int m, int kc) {   // rows 64B
    return m * 64 + ((kc ^ ((m >> 1) & 3)) << 4);
}
__device__ __forceinline__ int b_off(int k, int nc) {   // rows 256B, nc 0..15
    return k * 256 + ((nc ^ (k & 7)) << 4);
}
__device__ __forceinline__ uint32_t smem_u32(const void* p) {
    uint32_t a;
    asm("{ .reg .u64 t; cvta.to.shared.u64 t, %1; cvt.u32.u64 %0, t; }"
        : "=r"(a) : "l"(p));
    return a;
}
__device__ __forceinline__ void ldsm4(uint32_t* r, uint32_t addr) {
    asm volatile("ldmatrix.sync.aligned.m8n8.x4.shared.b16 {%0,%1,%2,%3}, [%4];"
                 : "=r"(r[0]), "=r"(r[1]), "=r"(r[2]), "=r"(r[3]) : "r"(addr));
}
__device__ __forceinline__ void ldsm4t(uint32_t* r, uint32_t addr) {
    asm volatile("ldmatrix.sync.aligned.m8n8.x4.trans.shared.b16 {%0,%1,%2,%3}, [%4];"
                 : "=r"(r[0]), "=r"(r[1]), "=r"(r[2]), "=r"(r[3]) : "r"(addr));
}
__device__ __forceinline__ void mma_f16(float* d, const uint32_t* a, const uint32_t* b) {
    asm volatile(
        "mma.sync.aligned.m16n8k16.row.col.f32.f16.f16.f32 "
        "{%0,%1,%2,%3}, {%4,%5,%6,%7}, {%8,%9}, {%0,%1,%2,%3};"
        : "+f"(d[0]), "+f"(d[1]), "+f"(d[2]), "+f"(d[3])
        : "r"(a[0]), "r"(a[1]), "r"(a[2]), "r"(a[3]), "r"(b[0]), "r"(b[1]));
}
__device__ __forceinline__ void cp16(uint32_t dst, const void* src) {
    asm volatile("cp.async.cg.shared.global [%0], [%1], 16;" :: "r"(dst), "l"(src));
}
__device__ __forceinline__ void cp_commit() {
    asm volatile("cp.async.commit_group;" ::: "memory");
}
template<int N>
__device__ __forceinline__ void cp_wait() {
    asm volatile("cp.async.wait_group %0;" :: "n"(N) : "memory");
}

// ---------------- main GEMM kernel ----------------
// CTA 128x128, warp tile 64x32 (2 m-cols x 4 n-rows), 1-pass fp16, fp32 accum.
// Forced 2 CTAs/SM via launch_bounds for latency hiding.
// Two-level z indexing: off = (z/zMod)*s1 + (z%zMod)*s2 for A, B, C; bias by zr.
// OUTM: 0 = fp32 out, 2 = single f16 out.
template<int OUTM, bool GELU_, bool BIAS_>
__global__ __launch_bounds__(THREADS, 2)
void moe_gemm(const f16* __restrict__ Ab, const f16* __restrict__ Bb,
              float* __restrict__ Cf, f16* __restrict__ Ch,
              const float* __restrict__ biasBase,
              int lda, int ldb, int ldc, int KT, int zMod,
              long long sA1, long long sA2, long long sB1, long long sB2,
              long long sC1, long long sC2, long long sBias2)
{
    extern __shared__ char smem[];
    const int tid  = threadIdx.x;
    const int lane = tid & 31;
    const int wid  = tid >> 5;
    const int wm   = (wid & 1) * 64;
    const int wn   = (wid >> 1) * 32;

    const int z = blockIdx.z;
    const int zq = z / zMod, zr = z % zMod;
    const f16* A = Ab + zq * sA1 + zr * sA2;
    const f16* B = Bb + zq * sB1 + zr * sB2;
    const long long coff = zq * sC1 + zr * sC2;
    const float* bias = BIAS_ ? biasBase + zr * sBias2 : nullptr;

    const int m0 = blockIdx.y * BM;
    const int n0 = blockIdx.x * BN;
    const uint32_t sbase = smem_u32(smem);

    float acc[4][4][4];
#pragma unroll
    for (int i = 0; i < 4; i++)
#pragma unroll
        for (int j = 0; j < 4; j++)
#pragma unroll
            for (int c = 0; c < 4; c++) acc[i][j][c] = 0.f;

    auto issue = [&](int it) {
        if (it < KT) {
            const uint32_t st = sbase + (it & (NSTG - 1)) * STAGE;
            const int k0 = it * BK;
#pragma unroll
            for (int i = 0; i < 2; i++) {
                int c = tid + i * THREADS;          // 512 chunks A
                int m = c >> 2, kc = c & 3;
                cp16(st + a_off(m, kc),
                     A + (size_t)(m0 + m) * lda + k0 + kc * 8);
            }
#pragma unroll
            for (int i = 0; i < 2; i++) {
                int c = tid + i * THREADS;          // 512 chunks B
                int k = c >> 4, nc = c & 15;
                cp16(st + OFF_B + b_off(k, nc),
                     B + (size_t)(k0 + k) * ldb + n0 + nc * 8);
            }
        }
        cp_commit();
    };

    issue(0); issue(1); issue(2);

    for (int it = 0; it < KT; ++it) {
        cp_wait<2>();
        __syncthreads();
        issue(it + 3);

        const uint32_t cur = sbase + (it & (NSTG - 1)) * STAGE;
#pragma unroll
        for (int kh = 0; kh < 2; kh++) {
            uint32_t ar[4][4];
#pragma unroll
            for (int mf = 0; mf < 4; mf++) {
                int row = wm + mf * 16 + (lane & 15);
                int chunk = kh * 2 + (lane >> 4);
                ldsm4(ar[mf], cur + a_off(row, chunk));
            }
            uint32_t br[2][4];
#pragma unroll
            for (int nb = 0; nb < 2; nb++) {
                int k = kh * 16 + ((lane >> 3) & 1) * 8 + (lane & 7);
                int nchunk = ((wn + nb * 16) >> 3) + (lane >> 4);
                ldsm4t(br[nb], cur + OFF_B + b_off(k, nchunk));
            }
#pragma unroll
            for (int mf = 0; mf < 4; mf++)
#pragma unroll
                for (int nf = 0; nf < 4; nf++)
                    mma_f16(acc[mf][nf], ar[mf], &br[nf >> 1][(nf & 1) * 2]);
        }
    }

    // ---- epilogue ----
    const int g = lane >> 2, t = lane & 3;
#pragma unroll
    for (int mf = 0; mf < 4; mf++) {
#pragma unroll
        for (int nf = 0; nf < 4; nf++) {
            int row = m0 + wm + mf * 16 + g;
            int col = n0 + wn + nf * 8 + t * 2;
            float v0 = acc[mf][nf][0], v1 = acc[mf][nf][1];
            float v2 = acc[mf][nf][2], v3 = acc[mf][nf][3];
            if (BIAS_) {
                float2 bv = *reinterpret_cast<const float2*>(bias + col);
                v0 += bv.x; v1 += bv.y; v2 += bv.x; v3 += bv.y;
            }
            if (GELU_) {
                v0 = 0.5f * v0 * (1.0f + erff(v0 * 0.70710678118654752f));
                v1 = 0.5f * v1 * (1.0f + erff(v1 * 0.70710678118654752f));
                v2 = 0.5f * v2 * (1.0f + erff(v2 * 0.70710678118654752f));
                v3 = 0.5f * v3 * (1.0f + erff(v3 * 0.70710678118654752f));
            }
            size_t o0 = (size_t)(coff + (size_t)row * ldc + col);
            size_t o1 = (size_t)(coff + (size_t)(row + 8) * ldc + col);
            if (OUTM == 0) {
                *reinterpret_cast<float2*>(Cf + o0) = make_float2(v0, v1);
                *reinterpret_cast<float2*>(Cf + o1) = make_float2(v2, v3);
            } else {
                *reinterpret_cast<uint32_t*>(Ch + o0) = pack_h2(v0, v1);
                *reinterpret_cast<uint32_t*>(Ch + o1) = pack_h2(v2, v3);
            }
        }
    }
}

// ---------------- launcher ----------------
extern "C" void kernel_launch(void* const* d_in, const int* in_sizes, int n_in,
                              void* d_out, int out_size)
{
    const float* x     = (const float*)d_in[0];
    const float* dmask = (const float*)d_in[1];
    const float* comb  = (const float*)d_in[2];
    const float* w1    = (const float*)d_in[3];
    const float* b1    = (const float*)d_in[4];
    const float* w2f   = (const float*)d_in[5];
    const float* b2    = (const float*)d_in[6];
    float* out = (float*)d_out;

    f16 *dmT, *cmb, *xs, *w1s, *w2s, *xd, *hh, *yy;
    cudaGetSymbolAddress((void**)&dmT, g_dmT);
    cudaGetSymbolAddress((void**)&cmb, g_cmb);
    cudaGetSymbolAddress((void**)&xs,  g_x);
    cudaGetSymbolAddress((void**)&w1s, g_w1);
    cudaGetSymbolAddress((void**)&w2s, g_w2);
    cudaGetSymbolAddress((void**)&xd,  g_xd);
    cudaGetSymbolAddress((void**)&hh,  g_h);
    cudaGetSymbolAddress((void**)&yy,  g_y);

    cudaFuncSetAttribute(moe_gemm<2, false, false>,
                         cudaFuncAttributeMaxDynamicSharedMemorySize, SMEM_TOTAL);
    cudaFuncSetAttribute(moe_gemm<2, true,  true>,
                         cudaFuncAttributeMaxDynamicSharedMemorySize, SMEM_TOTAL);
    cudaFuncSetAttribute(moe_gemm<0, false, true>,
                         cudaFuncAttributeMaxDynamicSharedMemorySize, SMEM_TOTAL);

    // ---- conversions (all single fp16) ----
    tr_one<<<dim3(ECDIM / 32, TDIM / 64, BDIM), 256>>>(dmask, dmT, TDIM, ECDIM);
    {
        long long n4 = (long long)BDIM * TDIM * ECDIM / 4;
        conv_ew<<<(unsigned)((n4 + 255) / 256), 256>>>(comb, cmb, n4);
    }
    {
        long long n4 = (long long)BDIM * TDIM * DDIM / 4;
        conv_ew<<<(unsigned)((n4 + 255) / 256), 256>>>(x, xs, n4);
    }
    {
        long long n4 = (long long)EDIM * DDIM * HEDIM / 4;
        conv_ew<<<(unsigned)((n4 + 255) / 256), 256>>>(w1, w1s, n4);
        conv_ew<<<(unsigned)((n4 + 255) / 256), 256>>>(w2f, w2s, n4);
    }

    // ---- K1: xd[b][EC][D] = dmT[b][EC][T] @ x[b][T][D] ----
    moe_gemm<2, false, false>
        <<<dim3(DDIM / BN, ECDIM / BM, BDIM), THREADS, SMEM_TOTAL>>>(
        dmT, xs, nullptr, xd, nullptr,
        TDIM, DDIM, DDIM, TDIM / BK, /*zMod*/ 1,
        (long long)ECDIM * TDIM, 0, (long long)TDIM * DDIM, 0,
        (long long)ECDIM * DDIM, 0, 0);

    // ---- K2: h[b,e][C][HE] = gelu(xd_{b,e}[C][D] @ w1_e[D][HE] + b1_e) ----
    moe_gemm<2, true, true>
        <<<dim3(HEDIM / BN, CDIM / BM, BDIM * EDIM), THREADS, SMEM_TOTAL>>>(
        xd, w1s, nullptr, hh, b1,
        DDIM, HEDIM, HEDIM, DDIM / BK, /*zMod*/ EDIM,
        (long long)EDIM * CDIM * DDIM, (long long)CDIM * DDIM,
        0, (long long)DDIM * HEDIM,
        (long long)EDIM * CDIM * HEDIM, (long long)CDIM * HEDIM,
        (long long)HEDIM);

    // ---- K3: y[b,e][C][O] = h_{b,e}[C][HE] @ w2_e[HE][O] ----
    moe_gemm<2, false, false>
        <<<dim3(ODIM / BN, CDIM / BM, BDIM * EDIM), THREADS, SMEM_TOTAL>>>(
        hh, w2s, nullptr, yy, nullptr,
        HEDIM, ODIM, ODIM, HEDIM / BK, /*zMod*/ EDIM,
        (long long)EDIM * CDIM * HEDIM, (long long)CDIM * HEDIM,
        0, (long long)HEDIM * ODIM,
        (long long)EDIM * CDIM * ODIM, (long long)CDIM * ODIM,
        0);

    // ---- K4: out[b][T][O] = comb[b][T][EC] @ y[b][EC][O] + b2 ----
    moe_gemm<0, false, true>
        <<<dim3(ODIM / BN, TDIM / BM, BDIM), THREADS, SMEM_TOTAL>>>(
        cmb, yy, out, nullptr, b2,
        ECDIM, ODIM, ODIM, ECDIM / BK, /*zMod*/ 1,
        (long long)TDIM * ECDIM, 0, (long long)ECDIM * ODIM, 0,
        (long long)TDIM * ODIM, 0, 0);
}